// round 10
// baseline (speedup 1.0000x reference)
#include <cuda_runtime.h>
#include <cuda_bf16.h>
#include <cstdint>

#define TRAJ      25
#define NT        10
#define NS        10
#define GDIM      200
#define GD2       (GDIM * GDIM)
#define MAP_ELEMS 8000000
#define VFOV_C    0.3490658503988659f
#define MAX_BT    (1024 * TRAJ * NT)   // supports outer up to 1024

// Staging: packed (pos_voxel.xyz, pen) and (gdir_voxel.xyz, 0) per (b,t).
__device__ float4 g_pos4[MAX_BT];
__device__ float4 g_gd4[MAX_BT];

// ---------- kernel 1: per-(b,t) prelude ----------
__global__ __launch_bounds__(256) void prelude_kernel(
    const float* __restrict__ Df, const float* __restrict__ Dp,
    const float* __restrict__ goal, const float* __restrict__ L,
    const float* __restrict__ minb, const int* __restrict__ map_id,
    float* __restrict__ out, int n_bt)
{
    const int n = blockIdx.x * blockDim.x + threadIdx.x;
    if (n >= n_bt) return;
    const int b  = n / NT;
    const int it = n - b * NT;
    const int o  = b / TRAJ;

    const float t = 0.66f + (float)it * ((1.32f - 0.66f) / 9.0f);

    float pos[3], vel[3];
    #pragma unroll
    for (int c = 0; c < 3; c++) {
        const float d0 = __ldg(Df + b * 9 + c * 3 + 0);
        const float d1 = __ldg(Df + b * 9 + c * 3 + 1);
        const float d2 = __ldg(Df + b * 9 + c * 3 + 2);
        const float d3 = __ldg(Dp + b * 9 + c * 3 + 0);
        const float d4 = __ldg(Dp + b * 9 + c * 3 + 1);
        const float d5 = __ldg(Dp + b * 9 + c * 3 + 2);
        float coe[6];
        #pragma unroll
        for (int i = 0; i < 6; i++) {
            coe[i] = __ldg(L + i * 6 + 0) * d0 + __ldg(L + i * 6 + 1) * d1
                   + __ldg(L + i * 6 + 2) * d2 + __ldg(L + i * 6 + 3) * d3
                   + __ldg(L + i * 6 + 4) * d4 + __ldg(L + i * 6 + 5) * d5;
        }
        float p = coe[5];
        p = p * t + coe[4];
        p = p * t + coe[3];
        p = p * t + coe[2];
        p = p * t + coe[1];
        p = p * t + coe[0];
        pos[c] = p;
        float v = 5.0f * coe[5];
        v = v * t + 4.0f * coe[4];
        v = v * t + 3.0f * coe[3];
        v = v * t + 2.0f * coe[2];
        v = v * t + coe[1];
        vel[c] = v;
    }

    const float gx0 = __ldg(goal + (long long)o * TRAJ * 3 + 0);
    const float gy0 = __ldg(goal + (long long)o * TRAJ * 3 + 1);
    const float gz0 = __ldg(goal + (long long)o * TRAJ * 3 + 2);
    const float gdx = gx0 - pos[0];
    const float gdy = gy0 - pos[1];
    const float gdz = gz0 - pos[2];

    const float pg = atan2f(gdz, sqrtf(gdx * gdx + gdy * gdy + 1e-6f));
    const float pv = atan2f(vel[2], sqrtf(vel[0] * vel[0] + vel[1] * vel[1] + 1e-6f));
    const float pen = fmaxf(fabsf(pg - pv) - VFOV_C, 0.0f);

    const int   m   = __ldg(map_id + o);
    const float mb0 = __ldg(minb + m * 3 + 0);
    const float mb1 = __ldg(minb + m * 3 + 1);
    const float mb2 = __ldg(minb + m * 3 + 2);

    g_pos4[n] = make_float4((pos[0] - mb0) * 5.0f,
                            (pos[1] - mb1) * 5.0f,
                            (pos[2] - mb2) * 5.0f, pen);
    g_gd4[n]  = make_float4(gdx * 5.0f, gdy * 5.0f, gdz * 5.0f, 0.0f);

    if (it == 0) out[b] = 0.0f;   // zero-init before gather kernel's atomics
}

// ---------- kernel 2: ONE trilinear sample/thread, vectorized corners -----
// grid (outer, NS); tid<250 -> (traj j, time it); sample s = blockIdx.y.
// Max occupancy (low regs, no residency cap) x vectorized fetch: each warp
// keeps ~5 independent line-requests in flight at ~45 resident warps/SM.
__global__ __launch_bounds__(256) void gather_kernel(
    const float* __restrict__ sdf, const int* __restrict__ map_id,
    float* __restrict__ out)
{
    const int o   = blockIdx.x;
    const int s   = blockIdx.y;
    const int tid = threadIdx.x;

    __shared__ float sC[TRAJ * NT];

    float w = 0.0f;
    if (tid < TRAJ * NT) {
        const int n = (o * TRAJ) * NT + tid;

        const float4 p4 = __ldg(g_pos4 + n);
        const float4 g4 = __ldg(g_gd4 + n);

        const float* __restrict__ map =
            sdf + (long long)__ldg(map_id + o) * MAP_ELEMS;

        const float a  = (float)s * (1.0f / 9.0f);
        const float vx = p4.x + a * g4.x;
        const float vy = p4.y + a * g4.y;
        const float vz = p4.z + a * g4.z;

        const bool valid = (vx > 0.5f) && (vx < (float)GDIM - 1.5f)
                        && (vy > 0.5f) && (vy < (float)GDIM - 1.5f)
                        && (vz > 0.5f) && (vz < (float)GDIM - 1.5f);

        const float x0f = fminf(fmaxf(floorf(vx), 0.0f), (float)(GDIM - 2));
        const float y0f = fminf(fmaxf(floorf(vy), 0.0f), (float)(GDIM - 2));
        const float z0f = fminf(fmaxf(floorf(vz), 0.0f), (float)(GDIM - 2));
        const float fx = vx - x0f, fy = vy - y0f, fz = vz - z0f;
        const int x0 = valid ? (int)x0f : 0;
        const int y0 = valid ? (int)y0f : 0;
        const int z0 = valid ? (int)z0f : 0;
        const int ph = x0 & 3;                       // 16B alignment phase
        const int ab = z0 * GD2 + y0 * GDIM + (x0 & ~3);

        // 4 independent aligned float4 row loads + predicated phase-3 patch
        const float4 q0 = __ldg((const float4*)(map + ab));
        const float4 q1 = __ldg((const float4*)(map + ab + GDIM));
        const float4 q2 = __ldg((const float4*)(map + ab + GD2));
        const float4 q3 = __ldg((const float4*)(map + ab + GD2 + GDIM));
        const bool need = (ph == 3);
        const float e0 = need ? __ldg(map + ab + 4) : 0.0f;
        const float e1 = need ? __ldg(map + ab + GDIM + 4) : 0.0f;
        const float e2 = need ? __ldg(map + ab + GD2 + 4) : 0.0f;
        const float e3 = need ? __ldg(map + ab + GD2 + GDIM + 4) : 0.0f;

        float lo[4], hi[4];
        {
            const float4 q[4] = {q0, q1, q2, q3};
            const float  e[4] = {e0, e1, e2, e3};
            #pragma unroll
            for (int r = 0; r < 4; r++) {
                lo[r] = (ph == 0) ? q[r].x : (ph == 1) ? q[r].y
                      : (ph == 2) ? q[r].z : q[r].w;
                hi[r] = (ph == 0) ? q[r].y : (ph == 1) ? q[r].z
                      : (ph == 2) ? q[r].w : e[r];
            }
        }

        const float omx = 1.0f - fx, omy = 1.0f - fy;
        const float l0 = (lo[0] * omx + hi[0] * fx) * omy
                       + (lo[1] * omx + hi[1] * fx) * fy;
        const float l1 = (lo[2] * omx + hi[2] * fx) * omy
                       + (lo[3] * omx + hi[3] * fx) * fy;
        const float dist = l0 * (1.0f - fz) + l1 * fz;
        const float cost = valid ? __expf(-(dist - 0.6f) * (1.0f / 0.3f))
                                 : 0.0f;
        w = 0.2f * fmaxf(0.2f - cost, 0.0f);

        if (s == 0) w += 0.5f * p4.w;   // fold pitch term once
        sC[tid] = w;
    }
    __syncthreads();

    if (tid < TRAJ) {
        float v = 0.0f;
        #pragma unroll
        for (int k = 0; k < NT; k++) v += sC[tid * NT + k];
        atomicAdd(&out[o * TRAJ + tid], v);
    }
}

extern "C" void kernel_launch(void* const* d_in, const int* in_sizes, int n_in,
                              void* d_out, int out_size)
{
    const float* Df     = (const float*)d_in[0];
    const float* Dp     = (const float*)d_in[1];
    const float* goal   = (const float*)d_in[2];
    const float* L      = (const float*)d_in[3];
    const float* sdf    = (const float*)d_in[4];
    const float* minb   = (const float*)d_in[5];
    const int*   map_id = (const int*)d_in[6];
    float* out = (float*)d_out;

    const int outer = in_sizes[6];
    const int n_bt  = outer * TRAJ * NT;

    prelude_kernel<<<(n_bt + 255) / 256, 256>>>(Df, Dp, goal, L, minb, map_id,
                                                out, n_bt);
    dim3 grid(outer, NS);
    gather_kernel<<<grid, 256>>>(sdf, map_id, out);
}